// round 1
// baseline (speedup 1.0000x reference)
#include <cuda_runtime.h>
#include <cuda_bf16.h>

// ---------------- Problem constants ----------------
#define B_SZ     4
#define L_SZ     4096
#define DIM      768
#define D_STATE  16
#define D_CONV   4
#define D_INNER  1536        // EXPAND * DIM
#define DT_RANK  48
#define E2       (2*D_INNER) // 3072
#define NTOK     (B_SZ*L_SZ) // 16384
#define XDBL_C   (DT_RANK + 2*D_STATE) // 80

// ---------------- Scratch (static device memory; allocation-free) ----------------
__device__ float g_xz  [(size_t)NTOK * E2];            // (b,l,3072)
__device__ float g_xc  [2 * (size_t)NTOK * D_INNER];   // per-dir conv+silu output (scan coords)
__device__ float g_dt  [2 * (size_t)NTOK * D_INNER];   // per-dir softplus(dt)
__device__ float g_xdbl[2 * (size_t)NTOK * XDBL_C];    // per-dir (dt_r | B | C)
__device__ float g_y   [2 * (size_t)NTOK * D_INNER];   // per-dir y*silu(z), stored at ORIGINAL l

// ---------------- helpers ----------------
__device__ __forceinline__ float softplusf(float x) {
    return (x > 20.f) ? x : log1pf(__expf(x));
}
__device__ __forceinline__ float siluf(float x) {
    return x / (1.f + __expf(-x));
}

// ---------------- Generic SGEMM:  C[m,n] = epi( sum_k Aeff[m,k]*B[n,k] + bias[n] ) ----------------
// Aeff = A (+ A2 if non-null).  A: M x K (row stride lda), B: N x K (row stride ldb).
// Requires: M % 128 == 0, K % 8 == 0. N arbitrary (predicated).
#define GBM 128
#define GBN 128
#define GBK 8
__global__ __launch_bounds__(256) void sgemm_bt(
    const float* __restrict__ A, int lda,
    const float* __restrict__ A2,
    const float* __restrict__ Bm, int ldb,
    const float* __restrict__ bias,
    float* __restrict__ C, int ldc,
    int M, int N, int K, int epi)
{
    __shared__ __align__(16) float As[GBK][GBM];
    __shared__ __align__(16) float Bs[GBK][GBN];

    const int tid = threadIdx.x;
    const int bm = blockIdx.y * GBM;
    const int bn = blockIdx.x * GBN;
    const int ty = tid >> 4;       // 0..15
    const int tx = tid & 15;       // 0..15

    const int arow = tid >> 1;         // 0..127
    const int acol = (tid & 1) * 4;    // 0 or 4
    const int brow = tid >> 1;
    const int bcol = (tid & 1) * 4;

    const float* Aptr  = A  + (size_t)(bm + arow) * lda + acol;
    const float* A2ptr = A2 ? (A2 + (size_t)(bm + arow) * lda + acol) : nullptr;
    const bool bvalid = (bn + brow) < N;
    const float* Bptr = Bm + (size_t)(bn + brow) * ldb + bcol;

    float acc[8][8];
    #pragma unroll
    for (int i = 0; i < 8; i++)
        #pragma unroll
        for (int j = 0; j < 8; j++) acc[i][j] = 0.f;

    for (int k0 = 0; k0 < K; k0 += GBK) {
        float4 av = *(const float4*)(Aptr + k0);
        if (A2ptr) {
            float4 a2 = *(const float4*)(A2ptr + k0);
            av.x += a2.x; av.y += a2.y; av.z += a2.z; av.w += a2.w;
        }
        float4 bv = make_float4(0.f, 0.f, 0.f, 0.f);
        if (bvalid) bv = *(const float4*)(Bptr + k0);

        __syncthreads();
        As[acol + 0][arow] = av.x;
        As[acol + 1][arow] = av.y;
        As[acol + 2][arow] = av.z;
        As[acol + 3][arow] = av.w;
        Bs[bcol + 0][brow] = bv.x;
        Bs[bcol + 1][brow] = bv.y;
        Bs[bcol + 2][brow] = bv.z;
        Bs[bcol + 3][brow] = bv.w;
        __syncthreads();

        #pragma unroll
        for (int k = 0; k < GBK; k++) {
            float4 a0 = *(const float4*)&As[k][ty * 8];
            float4 a1 = *(const float4*)&As[k][ty * 8 + 4];
            float4 b0 = *(const float4*)&Bs[k][tx * 8];
            float4 b1 = *(const float4*)&Bs[k][tx * 8 + 4];
            float ar[8] = {a0.x, a0.y, a0.z, a0.w, a1.x, a1.y, a1.z, a1.w};
            float br[8] = {b0.x, b0.y, b0.z, b0.w, b1.x, b1.y, b1.z, b1.w};
            #pragma unroll
            for (int i = 0; i < 8; i++)
                #pragma unroll
                for (int j = 0; j < 8; j++)
                    acc[i][j] += ar[i] * br[j];
        }
    }

    #pragma unroll
    for (int i = 0; i < 8; i++) {
        const int m = bm + ty * 8 + i;
        #pragma unroll
        for (int j = 0; j < 8; j++) {
            const int n = bn + tx * 8 + j;
            if (n < N) {
                float v = acc[i][j];
                if (bias) v += bias[n];
                if (epi == 1) v = softplusf(v);
                C[(size_t)m * ldc + n] = v;
            }
        }
    }
}

// ---------------- Causal depthwise conv (k=4) + SiLU, both directions ----------------
// dir=1 operates on time-reversed input; output stored in scan coordinates.
__global__ void conv_silu_kernel(
    const float* __restrict__ wf, const float* __restrict__ bf,
    const float* __restrict__ wb, const float* __restrict__ bb)
{
    const int dir = blockIdx.y;
    const size_t idx = (size_t)blockIdx.x * blockDim.x + threadIdx.x;
    if (idx >= (size_t)NTOK * D_INNER) return;
    const int d = (int)(idx % D_INNER);
    const size_t bl = idx / D_INNER;
    const int l = (int)(bl % L_SZ);
    const int b = (int)(bl / L_SZ);

    const float* w = dir ? wb : wf;
    float acc = dir ? bb[d] : bf[d];
    #pragma unroll
    for (int j = 0; j < D_CONV; j++) {
        const int m = l - (D_CONV - 1) + j;
        if (m >= 0) {
            const int src = dir ? (L_SZ - 1 - m) : m;
            acc += w[d * D_CONV + j] * g_xz[((size_t)b * L_SZ + src) * E2 + d];
        }
    }
    g_xc[((size_t)dir * NTOK + bl) * D_INNER + d] = siluf(acc);
}

// ---------------- Selective scan (sequential over L), fused gate + reversal ----------------
// One thread per (dir,b,d). 16 states in registers. B/C staged in smem per 64-step chunk.
#define SCHUNK 64
__global__ __launch_bounds__(128) void scan_kernel(
    const float* __restrict__ A_log_f, const float* __restrict__ D_f,
    const float* __restrict__ A_log_b, const float* __restrict__ D_b)
{
    const int dir = blockIdx.z;
    const int b   = blockIdx.y;
    const int d   = blockIdx.x * blockDim.x + threadIdx.x;
    const int tid = threadIdx.x;

    const size_t dirTok = (size_t)dir * NTOK;
    const float* xc   = g_xc   + dirTok * D_INNER;
    const float* dtp  = g_dt   + dirTok * D_INNER;
    const float* xdbl = g_xdbl + dirTok * XDBL_C;
    float*       yout = g_y    + dirTok * D_INNER;
    const float* Alog = dir ? A_log_b : A_log_f;
    const float* Dv   = dir ? D_b     : D_f;

    float A[D_STATE];
    #pragma unroll
    for (int n = 0; n < D_STATE; n++) A[n] = -__expf(Alog[d * D_STATE + n]);
    const float Dd = Dv[d];

    float h[D_STATE];
    #pragma unroll
    for (int n = 0; n < D_STATE; n++) h[n] = 0.f;

    __shared__ float sBC[SCHUNK][2 * D_STATE];

    for (int l0 = 0; l0 < L_SZ; l0 += SCHUNK) {
        __syncthreads();
        for (int i = tid; i < SCHUNK * 2 * D_STATE; i += blockDim.x) {
            const int t = i >> 5, c = i & 31;
            sBC[t][c] = xdbl[((size_t)b * L_SZ + l0 + t) * XDBL_C + DT_RANK + c];
        }
        __syncthreads();

        for (int t = 0; t < SCHUNK; t++) {
            const int l = l0 + t;
            const size_t base = ((size_t)b * L_SZ + l) * D_INNER + d;
            const float u   = xc[base];
            const float dtv = dtp[base];
            const float dtu = dtv * u;
            float y = 0.f;
            #pragma unroll
            for (int n = 0; n < D_STATE; n++) {
                const float dA = __expf(dtv * A[n]);
                h[n] = h[n] * dA + dtu * sBC[t][n];
                y += h[n] * sBC[t][D_STATE + n];
            }
            y += u * Dd;
            const int lsrc = dir ? (L_SZ - 1 - l) : l;   // original time index
            const float zv = g_xz[((size_t)b * L_SZ + lsrc) * E2 + D_INNER + d];
            yout[((size_t)b * L_SZ + lsrc) * D_INNER + d] = y * siluf(zv);
        }
    }
}

// ---------------- Launch ----------------
extern "C" void kernel_launch(void* const* d_in, const int* in_sizes, int n_in,
                              void* d_out, int out_size)
{
    const float* x            = (const float*)d_in[0];
    const float* in_proj_w    = (const float*)d_in[1];
    const float* out_proj_w   = (const float*)d_in[2];
    const float* conv1d_w     = (const float*)d_in[3];
    const float* conv1d_bias  = (const float*)d_in[4];
    const float* x_proj_w     = (const float*)d_in[5];
    const float* dt_proj_w    = (const float*)d_in[6];
    const float* dt_proj_bias = (const float*)d_in[7];
    const float* A_log        = (const float*)d_in[8];
    const float* Dvec         = (const float*)d_in[9];
    const float* conv1d_w_b   = (const float*)d_in[10];
    const float* conv1d_bias_b= (const float*)d_in[11];
    const float* x_proj_w_b   = (const float*)d_in[12];
    const float* dt_proj_w_b  = (const float*)d_in[13];
    const float* dt_proj_bias_b=(const float*)d_in[14];
    const float* A_log_b      = (const float*)d_in[15];
    const float* D_b          = (const float*)d_in[16];
    float* out = (float*)d_out;

    float *p_xz, *p_xc, *p_dt, *p_xdbl, *p_y;
    cudaGetSymbolAddress((void**)&p_xz,   g_xz);
    cudaGetSymbolAddress((void**)&p_xc,   g_xc);
    cudaGetSymbolAddress((void**)&p_dt,   g_dt);
    cudaGetSymbolAddress((void**)&p_xdbl, g_xdbl);
    cudaGetSymbolAddress((void**)&p_y,    g_y);

    const size_t tokDI = (size_t)NTOK * D_INNER;
    const size_t tokXD = (size_t)NTOK * XDBL_C;

    // 1) in_proj: xz = x @ W_in^T  (16384 x 3072, K=768)
    {
        dim3 grid(E2 / GBN, NTOK / GBM);
        sgemm_bt<<<grid, 256>>>(x, DIM, nullptr, in_proj_w, DIM, nullptr,
                                p_xz, E2, NTOK, E2, DIM, 0);
    }

    // 2) conv + silu, both directions
    {
        dim3 grid((unsigned)(((size_t)NTOK * D_INNER + 255) / 256), 2);
        conv_silu_kernel<<<grid, 256>>>(conv1d_w, conv1d_bias, conv1d_w_b, conv1d_bias_b);
    }

    // 3) x_proj per direction: x_dbl = xc @ x_proj_w^T  (16384 x 80, K=1536)
    {
        dim3 grid((XDBL_C + GBN - 1) / GBN, NTOK / GBM);
        sgemm_bt<<<grid, 256>>>(p_xc, D_INNER, nullptr, x_proj_w, D_INNER, nullptr,
                                p_xdbl, XDBL_C, NTOK, XDBL_C, D_INNER, 0);
        sgemm_bt<<<grid, 256>>>(p_xc + tokDI, D_INNER, nullptr, x_proj_w_b, D_INNER, nullptr,
                                p_xdbl + tokXD, XDBL_C, NTOK, XDBL_C, D_INNER, 0);
    }

    // 4) dt_proj per direction: dt = softplus(dt_r @ dt_w^T + bias)  (16384 x 1536, K=48)
    {
        dim3 grid(D_INNER / GBN, NTOK / GBM);
        sgemm_bt<<<grid, 256>>>(p_xdbl, XDBL_C, nullptr, dt_proj_w, DT_RANK, dt_proj_bias,
                                p_dt, D_INNER, NTOK, D_INNER, DT_RANK, 1);
        sgemm_bt<<<grid, 256>>>(p_xdbl + tokXD, XDBL_C, nullptr, dt_proj_w_b, DT_RANK, dt_proj_bias_b,
                                p_dt + tokDI, D_INNER, NTOK, D_INNER, DT_RANK, 1);
    }

    // 5) selective scan, both directions (grid.z)
    {
        dim3 grid(D_INNER / 128, B_SZ, 2);
        scan_kernel<<<grid, 128>>>(A_log, Dvec, A_log_b, D_b);
    }

    // 6) out_proj: out = (y_f + y_b) @ W_out^T  (16384 x 768, K=1536)
    {
        dim3 grid(DIM / GBN, NTOK / GBM);
        sgemm_bt<<<grid, 256>>>(p_y, D_INNER, p_y + tokDI, out_proj_w, D_INNER, nullptr,
                                out, DIM, NTOK, DIM, D_INNER, 0);
    }
}

// round 3
// speedup vs baseline: 1.2068x; 1.2068x over previous
#include <cuda_runtime.h>
#include <cuda_bf16.h>
#include <cstdint>

// ---------------- Problem constants ----------------
#define B_SZ     4
#define L_SZ     4096
#define DIM      768
#define D_STATE  16
#define D_CONV   4
#define D_INNER  1536
#define DT_RANK  48
#define E2       (2*D_INNER) // 3072
#define NTOK     (B_SZ*L_SZ) // 16384
#define XDBL_C   (DT_RANK + 2*D_STATE) // 80

// ---------------- Scratch ----------------
__device__ float g_xz  [(size_t)NTOK * E2];
__device__ float g_xc  [2 * (size_t)NTOK * D_INNER];
__device__ float g_dt  [2 * (size_t)NTOK * D_INNER];
__device__ float g_xdbl[2 * (size_t)NTOK * XDBL_C];
__device__ float g_y   [2 * (size_t)NTOK * D_INNER];

// ---------------- helpers ----------------
__device__ __forceinline__ float softplusf(float x) {
    return (x > 20.f) ? x : log1pf(__expf(x));
}
__device__ __forceinline__ float siluf(float x) {
    return x / (1.f + __expf(-x));
}
__device__ __forceinline__ uint32_t smem_u32(const void* p) {
    uint32_t a;
    asm("{ .reg .u64 t; cvta.to.shared.u64 t, %1; cvt.u32.u64 %0, t; }" : "=r"(a) : "l"(p));
    return a;
}
__device__ __forceinline__ void ldsm4(uint32_t* r, uint32_t addr) {
    asm volatile("ldmatrix.sync.aligned.m8n8.x4.shared.b16 {%0,%1,%2,%3}, [%4];"
        : "=r"(r[0]), "=r"(r[1]), "=r"(r[2]), "=r"(r[3]) : "r"(addr));
}
__device__ __forceinline__ void mma_bf16(float* c, const uint32_t* a, const uint32_t* b) {
    asm volatile("mma.sync.aligned.m16n8k16.row.col.f32.bf16.bf16.f32 "
        "{%0,%1,%2,%3}, {%4,%5,%6,%7}, {%8,%9}, {%0,%1,%2,%3};"
        : "+f"(c[0]), "+f"(c[1]), "+f"(c[2]), "+f"(c[3])
        : "r"(a[0]), "r"(a[1]), "r"(a[2]), "r"(a[3]), "r"(b[0]), "r"(b[1]));
}

// ---------------- split-bf16 HMMA GEMM ----------------
// C[m,n] = epi( sum_k (A[m,k](+A2[m,k])) * B[n,k] + bias[n] )
// A: M x K row-major, B: N x K row-major. M % 128 == 0. N, K arbitrary (K mult of 4).
#define BM 128
#define BN 128
#define BKC 32
#define PAD 40   // bf16 elements per smem row (80B stride -> conflict-free ldmatrix)

__global__ __launch_bounds__(256) void mmagemm_bt(
    const float* __restrict__ A, int lda,
    const float* __restrict__ A2,
    const float* __restrict__ Bm, int ldb,
    const float* __restrict__ bias,
    float* __restrict__ C, int ldc,
    int M, int N, int K, int epi)
{
    __shared__ __align__(16) __nv_bfloat16 sAh[BM * PAD];
    __shared__ __align__(16) __nv_bfloat16 sAl[BM * PAD];
    __shared__ __align__(16) __nv_bfloat16 sBh[BN * PAD];
    __shared__ __align__(16) __nv_bfloat16 sBl[BN * PAD];

    const int tid  = threadIdx.x;
    const int lane = tid & 31;
    const int wid  = tid >> 5;
    const int warpM = wid & 1;   // 2 M-warps (64 rows each)
    const int warpN = wid >> 1;  // 4 N-warps (32 cols each)
    const int bm = blockIdx.y * BM;
    const int bn = blockIdx.x * BN;

    const uint32_t uAh = smem_u32(sAh);
    const uint32_t uAl = smem_u32(sAl);
    const uint32_t uBh = smem_u32(sBh);
    const uint32_t uBl = smem_u32(sBl);

    float acc[4][4][4];
    #pragma unroll
    for (int f = 0; f < 4; f++)
        #pragma unroll
        for (int g = 0; g < 4; g++)
            #pragma unroll
            for (int i = 0; i < 4; i++) acc[f][g][i] = 0.f;

    // precomputed ldmatrix lane offsets (element units)
    // A frag f: row = warpM*64 + f*16 + (lane&15), col = ks*16 + (lane>>4)*8
    const int aRow = warpM * 64 + (lane & 15);
    const int aCol = (lane >> 4) * 8;
    // B frag pair p: row = warpN*32 + p*16 + (lane&7) + ((lane>>4)&1)*8, col = ks*16 + ((lane>>3)&1)*8
    const int bRow = warpN * 32 + (lane & 7) + ((lane >> 4) & 1) * 8;
    const int bCol = ((lane >> 3) & 1) * 8;

    for (int k0 = 0; k0 < K; k0 += BKC) {
        __syncthreads();
        // ---- global -> smem (fp32 -> bf16 hi/lo split) ----
        #pragma unroll
        for (int j = 0; j < 4; j++) {
            const int idx = tid + 256 * j;   // 0..1023
            const int row = idx >> 3;        // 0..127
            const int c4  = idx & 7;         // 0..7
            const int kk  = k0 + c4 * 4;

            float4 av = make_float4(0.f, 0.f, 0.f, 0.f);
            if (kk + 3 < K) {
                av = *(const float4*)(A + (size_t)(bm + row) * lda + kk);
                if (A2) {
                    float4 a2 = *(const float4*)(A2 + (size_t)(bm + row) * lda + kk);
                    av.x += a2.x; av.y += a2.y; av.z += a2.z; av.w += a2.w;
                }
            }
            {
                __nv_bfloat162 h01 = __floats2bfloat162_rn(av.x, av.y);
                __nv_bfloat162 h23 = __floats2bfloat162_rn(av.z, av.w);
                __nv_bfloat162 l01 = __floats2bfloat162_rn(av.x - __bfloat162float(h01.x),
                                                           av.y - __bfloat162float(h01.y));
                __nv_bfloat162 l23 = __floats2bfloat162_rn(av.z - __bfloat162float(h23.x),
                                                           av.w - __bfloat162float(h23.y));
                const int off = row * PAD + c4 * 4;
                *(uint2*)&sAh[off] = make_uint2(*(uint32_t*)&h01, *(uint32_t*)&h23);
                *(uint2*)&sAl[off] = make_uint2(*(uint32_t*)&l01, *(uint32_t*)&l23);
            }

            float4 bv = make_float4(0.f, 0.f, 0.f, 0.f);
            if ((bn + row) < N && kk + 3 < K)
                bv = *(const float4*)(Bm + (size_t)(bn + row) * ldb + kk);
            {
                __nv_bfloat162 h01 = __floats2bfloat162_rn(bv.x, bv.y);
                __nv_bfloat162 h23 = __floats2bfloat162_rn(bv.z, bv.w);
                __nv_bfloat162 l01 = __floats2bfloat162_rn(bv.x - __bfloat162float(h01.x),
                                                           bv.y - __bfloat162float(h01.y));
                __nv_bfloat162 l23 = __floats2bfloat162_rn(bv.z - __bfloat162float(h23.x),
                                                           bv.w - __bfloat162float(h23.y));
                const int off = row * PAD + c4 * 4;
                *(uint2*)&sBh[off] = make_uint2(*(uint32_t*)&h01, *(uint32_t*)&h23);
                *(uint2*)&sBl[off] = make_uint2(*(uint32_t*)&l01, *(uint32_t*)&l23);
            }
        }
        __syncthreads();

        // ---- compute: 2 k-steps of 16, 3 split passes ----
        #pragma unroll
        for (int ks = 0; ks < 2; ks++) {
            uint32_t ah[4][4], al[4][4], bh[4][2], bl[4][2];
            const int kc = ks * 16;

            #pragma unroll
            for (int f = 0; f < 4; f++) {
                const uint32_t aoff = (uint32_t)((aRow + f * 16) * PAD + kc + aCol) * 2;
                ldsm4(ah[f], uAh + aoff);
                ldsm4(al[f], uAl + aoff);
            }
            #pragma unroll
            for (int p = 0; p < 2; p++) {
                const uint32_t boff = (uint32_t)((bRow + p * 16) * PAD + kc + bCol) * 2;
                uint32_t r[4];
                ldsm4(r, uBh + boff);
                bh[2*p][0] = r[0]; bh[2*p][1] = r[1];
                bh[2*p+1][0] = r[2]; bh[2*p+1][1] = r[3];
                ldsm4(r, uBl + boff);
                bl[2*p][0] = r[0]; bl[2*p][1] = r[1];
                bl[2*p+1][0] = r[2]; bl[2*p+1][1] = r[3];
            }

            #pragma unroll
            for (int f = 0; f < 4; f++)
                #pragma unroll
                for (int g = 0; g < 4; g++) {
                    mma_bf16(acc[f][g], ah[f], bh[g]);
                    mma_bf16(acc[f][g], ah[f], bl[g]);
                    mma_bf16(acc[f][g], al[f], bh[g]);
                }
        }
    }

    // ---- epilogue: direct float2 stores (each quad covers a full 32B sector) ----
    #pragma unroll
    for (int f = 0; f < 4; f++) {
        const int r0 = bm + warpM * 64 + f * 16 + (lane >> 2);
        #pragma unroll
        for (int g = 0; g < 4; g++) {
            const int col = bn + warpN * 32 + g * 8 + 2 * (lane & 3);
            if (col < N) {
                float v0 = acc[f][g][0], v1 = acc[f][g][1];
                float v2 = acc[f][g][2], v3 = acc[f][g][3];
                if (bias) {
                    const float b0 = bias[col], b1 = bias[col + 1];
                    v0 += b0; v1 += b1; v2 += b0; v3 += b1;
                }
                if (epi == 1) {
                    v0 = softplusf(v0); v1 = softplusf(v1);
                    v2 = softplusf(v2); v3 = softplusf(v3);
                }
                *(float2*)(C + (size_t)r0 * ldc + col)       = make_float2(v0, v1);
                *(float2*)(C + (size_t)(r0 + 8) * ldc + col) = make_float2(v2, v3);
            }
        }
    }
}

// ---------------- Causal depthwise conv (k=4) + SiLU, both directions ----------------
__global__ void conv_silu_kernel(
    const float* __restrict__ wf, const float* __restrict__ bf,
    const float* __restrict__ wb, const float* __restrict__ bb)
{
    const int dir = blockIdx.y;
    const size_t idx = (size_t)blockIdx.x * blockDim.x + threadIdx.x;
    if (idx >= (size_t)NTOK * D_INNER) return;
    const int d = (int)(idx % D_INNER);
    const size_t bl = idx / D_INNER;
    const int l = (int)(bl % L_SZ);
    const int b = (int)(bl / L_SZ);

    const float* w = dir ? wb : wf;
    float acc = dir ? bb[d] : bf[d];
    #pragma unroll
    for (int j = 0; j < D_CONV; j++) {
        const int m = l - (D_CONV - 1) + j;
        if (m >= 0) {
            const int src = dir ? (L_SZ - 1 - m) : m;
            acc += w[d * D_CONV + j] * g_xz[((size_t)b * L_SZ + src) * E2 + d];
        }
    }
    g_xc[((size_t)dir * NTOK + bl) * D_INNER + d] = siluf(acc);
}

// ---------------- Selective scan ----------------
#define SCHUNK 64
__global__ __launch_bounds__(128) void scan_kernel(
    const float* __restrict__ A_log_f, const float* __restrict__ D_f,
    const float* __restrict__ A_log_b, const float* __restrict__ D_b)
{
    const int dir = blockIdx.z;
    const int b   = blockIdx.y;
    const int d   = blockIdx.x * blockDim.x + threadIdx.x;
    const int tid = threadIdx.x;

    const size_t dirTok = (size_t)dir * NTOK;
    const float* xc   = g_xc   + dirTok * D_INNER;
    const float* dtp  = g_dt   + dirTok * D_INNER;
    const float* xdbl = g_xdbl + dirTok * XDBL_C;
    float*       yout = g_y    + dirTok * D_INNER;
    const float* Alog = dir ? A_log_b : A_log_f;
    const float* Dv   = dir ? D_b     : D_f;

    float A[D_STATE];
    #pragma unroll
    for (int n = 0; n < D_STATE; n++) A[n] = -__expf(Alog[d * D_STATE + n]);
    const float Dd = Dv[d];

    float h[D_STATE];
    #pragma unroll
    for (int n = 0; n < D_STATE; n++) h[n] = 0.f;

    __shared__ float sBC[SCHUNK][2 * D_STATE];

    for (int l0 = 0; l0 < L_SZ; l0 += SCHUNK) {
        __syncthreads();
        for (int i = tid; i < SCHUNK * 2 * D_STATE; i += blockDim.x) {
            const int t = i >> 5, c = i & 31;
            sBC[t][c] = xdbl[((size_t)b * L_SZ + l0 + t) * XDBL_C + DT_RANK + c];
        }
        __syncthreads();

        for (int t = 0; t < SCHUNK; t++) {
            const int l = l0 + t;
            const size_t base = ((size_t)b * L_SZ + l) * D_INNER + d;
            const float u   = xc[base];
            const float dtv = dtp[base];
            const float dtu = dtv * u;
            float y = 0.f;
            #pragma unroll
            for (int n = 0; n < D_STATE; n++) {
                const float dA = __expf(dtv * A[n]);
                h[n] = h[n] * dA + dtu * sBC[t][n];
                y += h[n] * sBC[t][D_STATE + n];
            }
            y += u * Dd;
            const int lsrc = dir ? (L_SZ - 1 - l) : l;
            const float zv = g_xz[((size_t)b * L_SZ + lsrc) * E2 + D_INNER + d];
            yout[((size_t)b * L_SZ + lsrc) * D_INNER + d] = y * siluf(zv);
        }
    }
}

// ---------------- Launch ----------------
extern "C" void kernel_launch(void* const* d_in, const int* in_sizes, int n_in,
                              void* d_out, int out_size)
{
    const float* x            = (const float*)d_in[0];
    const float* in_proj_w    = (const float*)d_in[1];
    const float* out_proj_w   = (const float*)d_in[2];
    const float* conv1d_w     = (const float*)d_in[3];
    const float* conv1d_bias  = (const float*)d_in[4];
    const float* x_proj_w     = (const float*)d_in[5];
    const float* dt_proj_w    = (const float*)d_in[6];
    const float* dt_proj_bias = (const float*)d_in[7];
    const float* A_log        = (const float*)d_in[8];
    const float* Dvec         = (const float*)d_in[9];
    const float* conv1d_w_b   = (const float*)d_in[10];
    const float* conv1d_bias_b= (const float*)d_in[11];
    const float* x_proj_w_b   = (const float*)d_in[12];
    const float* dt_proj_w_b  = (const float*)d_in[13];
    const float* dt_proj_bias_b=(const float*)d_in[14];
    const float* A_log_b      = (const float*)d_in[15];
    const float* D_b          = (const float*)d_in[16];
    float* out = (float*)d_out;

    float *p_xz, *p_xc, *p_dt, *p_xdbl, *p_y;
    cudaGetSymbolAddress((void**)&p_xz,   g_xz);
    cudaGetSymbolAddress((void**)&p_xc,   g_xc);
    cudaGetSymbolAddress((void**)&p_dt,   g_dt);
    cudaGetSymbolAddress((void**)&p_xdbl, g_xdbl);
    cudaGetSymbolAddress((void**)&p_y,    g_y);

    const size_t tokDI = (size_t)NTOK * D_INNER;
    const size_t tokXD = (size_t)NTOK * XDBL_C;

    // 1) in_proj: xz = x @ W_in^T  (16384 x 3072, K=768)
    {
        dim3 grid(E2 / BN, NTOK / BM);
        mmagemm_bt<<<grid, 256>>>(x, DIM, nullptr, in_proj_w, DIM, nullptr,
                                  p_xz, E2, NTOK, E2, DIM, 0);
    }

    // 2) conv + silu, both directions
    {
        dim3 grid((unsigned)(((size_t)NTOK * D_INNER + 255) / 256), 2);
        conv_silu_kernel<<<grid, 256>>>(conv1d_w, conv1d_bias, conv1d_w_b, conv1d_bias_b);
    }

    // 3) x_proj per direction (16384 x 80, K=1536)
    {
        dim3 grid(1, NTOK / BM);
        mmagemm_bt<<<grid, 256>>>(p_xc, D_INNER, nullptr, x_proj_w, D_INNER, nullptr,
                                  p_xdbl, XDBL_C, NTOK, XDBL_C, D_INNER, 0);
        mmagemm_bt<<<grid, 256>>>(p_xc + tokDI, D_INNER, nullptr, x_proj_w_b, D_INNER, nullptr,
                                  p_xdbl + tokXD, XDBL_C, NTOK, XDBL_C, D_INNER, 0);
    }

    // 4) dt_proj per direction (16384 x 1536, K=48) + softplus
    {
        dim3 grid(D_INNER / BN, NTOK / BM);
        mmagemm_bt<<<grid, 256>>>(p_xdbl, XDBL_C, nullptr, dt_proj_w, DT_RANK, dt_proj_bias,
                                  p_dt, D_INNER, NTOK, D_INNER, DT_RANK, 1);
        mmagemm_bt<<<grid, 256>>>(p_xdbl + tokXD, XDBL_C, nullptr, dt_proj_w_b, DT_RANK, dt_proj_bias_b,
                                  p_dt + tokDI, D_INNER, NTOK, D_INNER, DT_RANK, 1);
    }

    // 5) selective scan
    {
        dim3 grid(D_INNER / 128, B_SZ, 2);
        scan_kernel<<<grid, 128>>>(A_log, Dvec, A_log_b, D_b);
    }

    // 6) out_proj: out = (y_f + y_b) @ W_out^T  (16384 x 768, K=1536)
    {
        dim3 grid(DIM / BN, NTOK / BM);
        mmagemm_bt<<<grid, 256>>>(p_y, D_INNER, p_y + tokDI, out_proj_w, D_INNER, nullptr,
                                  out, DIM, NTOK, DIM, D_INNER, 0);
    }
}

// round 4
// speedup vs baseline: 1.4546x; 1.2053x over previous
#include <cuda_runtime.h>
#include <cuda_bf16.h>
#include <cstdint>

// ---------------- Problem constants ----------------
#define B_SZ     4
#define L_SZ     4096
#define DIM      768
#define D_STATE  16
#define D_CONV   4
#define D_INNER  1536
#define DT_RANK  48
#define E2       (2*D_INNER) // 3072
#define NTOK     (B_SZ*L_SZ) // 16384
#define XDBL_C   (DT_RANK + 2*D_STATE) // 80

// ---------------- Scratch (static, allocation-free) ----------------
__device__ float g_xz  [(size_t)NTOK * E2];            // in_proj out (fp32): x half + z half
__device__ float g_dt  [2 * (size_t)NTOK * D_INNER];   // softplus(dt) per dir
__device__ float g_xdbl[2 * (size_t)NTOK * XDBL_C];    // (dt_r | B | C) per dir
__device__ float g_y   [2 * (size_t)NTOK * D_INNER];   // scan out per dir (original l)

// bf16 split buffers
__device__ __align__(16) __nv_bfloat16 s_xh [(size_t)NTOK * DIM];
__device__ __align__(16) __nv_bfloat16 s_xl [(size_t)NTOK * DIM];
__device__ __align__(16) __nv_bfloat16 s_wih[(size_t)E2 * DIM];
__device__ __align__(16) __nv_bfloat16 s_wil[(size_t)E2 * DIM];
__device__ __align__(16) __nv_bfloat16 s_woh[(size_t)DIM * D_INNER];
__device__ __align__(16) __nv_bfloat16 s_wol[(size_t)DIM * D_INNER];
__device__ __align__(16) __nv_bfloat16 s_wxh[2 * (size_t)XDBL_C * D_INNER];
__device__ __align__(16) __nv_bfloat16 s_wxl[2 * (size_t)XDBL_C * D_INNER];
__device__ __align__(16) __nv_bfloat16 s_wdh[2 * (size_t)D_INNER * DT_RANK];
__device__ __align__(16) __nv_bfloat16 s_wdl[2 * (size_t)D_INNER * DT_RANK];
__device__ __align__(16) __nv_bfloat16 s_xch[2 * (size_t)NTOK * D_INNER];
__device__ __align__(16) __nv_bfloat16 s_xcl[2 * (size_t)NTOK * D_INNER];
__device__ __align__(16) __nv_bfloat16 s_dtrh[2 * (size_t)NTOK * DT_RANK];
__device__ __align__(16) __nv_bfloat16 s_dtrl[2 * (size_t)NTOK * DT_RANK];
__device__ __align__(16) __nv_bfloat16 s_ysh[(size_t)NTOK * D_INNER];
__device__ __align__(16) __nv_bfloat16 s_ysl[(size_t)NTOK * D_INNER];

// ---------------- helpers ----------------
__device__ __forceinline__ float softplusf(float x) {
    return (x > 20.f) ? x : log1pf(__expf(x));
}
__device__ __forceinline__ float siluf(float x) {
    return x / (1.f + __expf(-x));
}
__device__ __forceinline__ uint32_t smem_u32(const void* p) {
    uint32_t a;
    asm("{ .reg .u64 t; cvta.to.shared.u64 t, %1; cvt.u32.u64 %0, t; }" : "=r"(a) : "l"(p));
    return a;
}
__device__ __forceinline__ void ldsm4(uint32_t* r, uint32_t addr) {
    asm volatile("ldmatrix.sync.aligned.m8n8.x4.shared.b16 {%0,%1,%2,%3}, [%4];"
        : "=r"(r[0]), "=r"(r[1]), "=r"(r[2]), "=r"(r[3]) : "r"(addr));
}
__device__ __forceinline__ void mma_bf16(float* c, const uint32_t* a, const uint32_t* b) {
    asm volatile("mma.sync.aligned.m16n8k16.row.col.f32.bf16.bf16.f32 "
        "{%0,%1,%2,%3}, {%4,%5,%6,%7}, {%8,%9}, {%0,%1,%2,%3};"
        : "+f"(c[0]), "+f"(c[1]), "+f"(c[2]), "+f"(c[3])
        : "r"(a[0]), "r"(a[1]), "r"(a[2]), "r"(a[3]), "r"(b[0]), "r"(b[1]));
}
__device__ __forceinline__ void cp16(uint32_t dst, const void* src, bool pred) {
    const int sz = pred ? 16 : 0;
    asm volatile("cp.async.cg.shared.global [%0], [%1], 16, %2;"
        :: "r"(dst), "l"(src), "r"(sz) : "memory");
}
__device__ __forceinline__ void split2(float v, __nv_bfloat16& h, __nv_bfloat16& l) {
    h = __float2bfloat16(v);
    l = __float2bfloat16(v - __bfloat162float(h));
}

// ---------------- conversion kernels ----------------
__global__ void cvt_split(const float* __restrict__ src,
                          __nv_bfloat16* __restrict__ h, __nv_bfloat16* __restrict__ l,
                          int n4)
{
    for (int i = blockIdx.x * blockDim.x + threadIdx.x; i < n4; i += gridDim.x * blockDim.x) {
        float4 v = ((const float4*)src)[i];
        __nv_bfloat16 h0,h1,h2,h3,l0,l1,l2,l3;
        split2(v.x,h0,l0); split2(v.y,h1,l1); split2(v.z,h2,l2); split2(v.w,h3,l3);
        __nv_bfloat162 hh01{h0,h1}, hh23{h2,h3}, ll01{l0,l1}, ll23{l2,l3};
        ((uint2*)h)[i] = make_uint2(*(uint32_t*)&hh01, *(uint32_t*)&hh23);
        ((uint2*)l)[i] = make_uint2(*(uint32_t*)&ll01, *(uint32_t*)&ll23);
    }
}

__global__ void cvt_add_split(const float* __restrict__ a, const float* __restrict__ b,
                              __nv_bfloat16* __restrict__ h, __nv_bfloat16* __restrict__ l,
                              int n4)
{
    for (int i = blockIdx.x * blockDim.x + threadIdx.x; i < n4; i += gridDim.x * blockDim.x) {
        float4 va = ((const float4*)a)[i];
        float4 vb = ((const float4*)b)[i];
        va.x += vb.x; va.y += vb.y; va.z += vb.z; va.w += vb.w;
        __nv_bfloat16 h0,h1,h2,h3,l0,l1,l2,l3;
        split2(va.x,h0,l0); split2(va.y,h1,l1); split2(va.z,h2,l2); split2(va.w,h3,l3);
        __nv_bfloat162 hh01{h0,h1}, hh23{h2,h3}, ll01{l0,l1}, ll23{l2,l3};
        ((uint2*)h)[i] = make_uint2(*(uint32_t*)&hh01, *(uint32_t*)&hh23);
        ((uint2*)l)[i] = make_uint2(*(uint32_t*)&ll01, *(uint32_t*)&ll23);
    }
}

// dt_r columns (0..47) of xdbl -> split bf16 [NTOK][48], both dirs via grid.y
__global__ void cvt_dtr(int dummy)
{
    const int dir = blockIdx.y;
    const float* src = g_xdbl + (size_t)dir * NTOK * XDBL_C;
    __nv_bfloat16* h = s_dtrh + (size_t)dir * NTOK * DT_RANK;
    __nv_bfloat16* l = s_dtrl + (size_t)dir * NTOK * DT_RANK;
    const int n = NTOK * (DT_RANK / 4);
    for (int i = blockIdx.x * blockDim.x + threadIdx.x; i < n; i += gridDim.x * blockDim.x) {
        const int row = i / (DT_RANK / 4);
        const int j   = i % (DT_RANK / 4);
        float4 v = *(const float4*)(src + (size_t)row * XDBL_C + j * 4);
        __nv_bfloat16 h0,h1,h2,h3,l0,l1,l2,l3;
        split2(v.x,h0,l0); split2(v.y,h1,l1); split2(v.z,h2,l2); split2(v.w,h3,l3);
        __nv_bfloat162 hh01{h0,h1}, hh23{h2,h3}, ll01{l0,l1}, ll23{l2,l3};
        ((uint2*)h)[(size_t)row * (DT_RANK/8) * 2 + j] = make_uint2(*(uint32_t*)&hh01, *(uint32_t*)&hh23);
        ((uint2*)l)[(size_t)row * (DT_RANK/8) * 2 + j] = make_uint2(*(uint32_t*)&ll01, *(uint32_t*)&ll23);
    }
}

// ---------------- cp.async double-buffered split-bf16 HMMA GEMM ----------------
// C[m,n] = epi( sum_k A[m,k]*B[n,k] + bias[n] ),  A ~ Ah+Al, B ~ Bh+Bl (bf16 splits)
#define BM 128
#define BN 128
#define BKC 32
#define PAD 40
#define OFF_AH 0
#define OFF_AL 10240
#define OFF_BH 20480
#define OFF_BL 30720
#define STAGE_B 40960

struct GArg {
    const __nv_bfloat16 *Ah, *Al, *Bh, *Bl;
    const float* bias;
    float* C;
};

__global__ __launch_bounds__(256, 2) void gemm_sp(
    GArg g0, GArg g1, int lda, int ldb, int ldc, int M, int N, int K, int epi)
{
    extern __shared__ char smem[];
    const uint32_t sbase = smem_u32(smem);
    const GArg g = (blockIdx.z == 0) ? g0 : g1;

    const int tid  = threadIdx.x;
    const int lane = tid & 31;
    const int wid  = tid >> 5;
    const int warpM = wid & 1;
    const int warpN = wid >> 1;
    const int bm = blockIdx.y * BM;
    const int bn = blockIdx.x * BN;

    float acc[4][4][4];
    #pragma unroll
    for (int f = 0; f < 4; f++)
        #pragma unroll
        for (int gg = 0; gg < 4; gg++)
            #pragma unroll
            for (int i = 0; i < 4; i++) acc[f][gg][i] = 0.f;

    const int aRow = warpM * 64 + (lane & 15);
    const int aCol = (lane >> 4) * 8;
    const int bRow = warpN * 32 + (lane & 7) + ((lane >> 4) & 1) * 8;
    const int bCol = ((lane >> 3) & 1) * 8;

    const int nch = (K + BKC - 1) / BKC;

    // chunk loader
    auto issue = [&](int c, int buf) {
        const int k0 = c * BKC;
        const uint32_t st = sbase + buf * STAGE_B;
        #pragma unroll
        for (int hh = 0; hh < 2; hh++) {
            const int ch  = tid + 256 * hh;   // 0..511
            const int row = ch >> 2;
            const int c16 = ch & 3;
            const int kk  = k0 + c16 * 8;
            const bool vA = kk < K;
            const bool vB = vA && ((bn + row) < N);
            const size_t aoff = vA ? ((size_t)(bm + row) * lda + kk) : 0;
            const size_t boff = vB ? ((size_t)(bn + row) * ldb + kk) : 0;
            const uint32_t so = (uint32_t)(row * (PAD*2) + c16 * 16);
            cp16(st + OFF_AH + so, g.Ah + aoff, vA);
            cp16(st + OFF_AL + so, g.Al + aoff, vA);
            cp16(st + OFF_BH + so, g.Bh + boff, vB);
            cp16(st + OFF_BL + so, g.Bl + boff, vB);
        }
    };

    issue(0, 0);
    asm volatile("cp.async.commit_group;" ::: "memory");

    for (int c = 0; c < nch; c++) {
        if (c + 1 < nch) issue(c + 1, (c + 1) & 1);
        asm volatile("cp.async.commit_group;" ::: "memory");
        asm volatile("cp.async.wait_group 1;" ::: "memory");
        __syncthreads();

        const uint32_t st = sbase + (c & 1) * STAGE_B;
        #pragma unroll
        for (int ks = 0; ks < 2; ks++) {
            const int kc = ks * 16;
            uint32_t a[4][4], b[4][2];
            // pass 1: Ah x Bh
            #pragma unroll
            for (int f = 0; f < 4; f++)
                ldsm4(a[f], st + OFF_AH + (uint32_t)((aRow + f*16) * PAD + kc + aCol) * 2);
            #pragma unroll
            for (int p = 0; p < 2; p++) {
                uint32_t r[4];
                ldsm4(r, st + OFF_BH + (uint32_t)((bRow + p*16) * PAD + kc + bCol) * 2);
                b[2*p][0] = r[0]; b[2*p][1] = r[1];
                b[2*p+1][0] = r[2]; b[2*p+1][1] = r[3];
            }
            #pragma unroll
            for (int f = 0; f < 4; f++)
                #pragma unroll
                for (int gg = 0; gg < 4; gg++) mma_bf16(acc[f][gg], a[f], b[gg]);
            // pass 2: Ah x Bl
            #pragma unroll
            for (int p = 0; p < 2; p++) {
                uint32_t r[4];
                ldsm4(r, st + OFF_BL + (uint32_t)((bRow + p*16) * PAD + kc + bCol) * 2);
                b[2*p][0] = r[0]; b[2*p][1] = r[1];
                b[2*p+1][0] = r[2]; b[2*p+1][1] = r[3];
            }
            #pragma unroll
            for (int f = 0; f < 4; f++)
                #pragma unroll
                for (int gg = 0; gg < 4; gg++) mma_bf16(acc[f][gg], a[f], b[gg]);
            // pass 3: Al x Bh
            #pragma unroll
            for (int f = 0; f < 4; f++)
                ldsm4(a[f], st + OFF_AL + (uint32_t)((aRow + f*16) * PAD + kc + aCol) * 2);
            #pragma unroll
            for (int p = 0; p < 2; p++) {
                uint32_t r[4];
                ldsm4(r, st + OFF_BH + (uint32_t)((bRow + p*16) * PAD + kc + bCol) * 2);
                b[2*p][0] = r[0]; b[2*p][1] = r[1];
                b[2*p+1][0] = r[2]; b[2*p+1][1] = r[3];
            }
            #pragma unroll
            for (int f = 0; f < 4; f++)
                #pragma unroll
                for (int gg = 0; gg < 4; gg++) mma_bf16(acc[f][gg], a[f], b[gg]);
        }
        __syncthreads();
    }

    // epilogue: direct float2 stores
    #pragma unroll
    for (int f = 0; f < 4; f++) {
        const int r0 = bm + warpM * 64 + f * 16 + (lane >> 2);
        #pragma unroll
        for (int gg = 0; gg < 4; gg++) {
            const int col = bn + warpN * 32 + gg * 8 + 2 * (lane & 3);
            if (col < N) {
                float v0 = acc[f][gg][0], v1 = acc[f][gg][1];
                float v2 = acc[f][gg][2], v3 = acc[f][gg][3];
                if (g.bias) {
                    const float b0 = g.bias[col], b1 = g.bias[col + 1];
                    v0 += b0; v1 += b1; v2 += b0; v3 += b1;
                }
                if (epi == 1) {
                    v0 = softplusf(v0); v1 = softplusf(v1);
                    v2 = softplusf(v2); v3 = softplusf(v3);
                }
                *(float2*)(g.C + (size_t)r0 * ldc + col)       = make_float2(v0, v1);
                *(float2*)(g.C + (size_t)(r0 + 8) * ldc + col) = make_float2(v2, v3);
            }
        }
    }
}

// ---------------- Causal depthwise conv (k=4) + SiLU -> split bf16, both dirs ----------------
__global__ void conv_silu_kernel(
    const float* __restrict__ wf, const float* __restrict__ bf,
    const float* __restrict__ wb, const float* __restrict__ bb)
{
    const int dir = blockIdx.y;
    const size_t idx = (size_t)blockIdx.x * blockDim.x + threadIdx.x;
    if (idx >= (size_t)NTOK * D_INNER) return;
    const int d = (int)(idx % D_INNER);
    const size_t bl = idx / D_INNER;
    const int l = (int)(bl % L_SZ);
    const int b = (int)(bl / L_SZ);

    const float* w = dir ? wb : wf;
    float acc = dir ? bb[d] : bf[d];
    #pragma unroll
    for (int j = 0; j < D_CONV; j++) {
        const int m = l - (D_CONV - 1) + j;
        if (m >= 0) {
            const int src = dir ? (L_SZ - 1 - m) : m;
            acc += w[d * D_CONV + j] * g_xz[((size_t)b * L_SZ + src) * E2 + d];
        }
    }
    const float v = siluf(acc);
    __nv_bfloat16 h, lo;
    split2(v, h, lo);
    const size_t o = ((size_t)dir * NTOK + bl) * D_INNER + d;
    s_xch[o] = h;
    s_xcl[o] = lo;
}

// ---------------- Selective scan ----------------
#define SCHUNK 64
__global__ __launch_bounds__(128) void scan_kernel(
    const float* __restrict__ A_log_f, const float* __restrict__ D_f,
    const float* __restrict__ A_log_b, const float* __restrict__ D_b)
{
    const int dir = blockIdx.z;
    const int b   = blockIdx.y;
    const int d   = blockIdx.x * blockDim.x + threadIdx.x;
    const int tid = threadIdx.x;

    const size_t dirTok = (size_t)dir * NTOK;
    const __nv_bfloat16* xch = s_xch + dirTok * D_INNER;
    const __nv_bfloat16* xcl = s_xcl + dirTok * D_INNER;
    const float* dtp  = g_dt   + dirTok * D_INNER;
    const float* xdbl = g_xdbl + dirTok * XDBL_C;
    float*       yout = g_y    + dirTok * D_INNER;
    const float* Alog = dir ? A_log_b : A_log_f;
    const float* Dv   = dir ? D_b     : D_f;

    float A[D_STATE];
    #pragma unroll
    for (int n = 0; n < D_STATE; n++) A[n] = -__expf(Alog[d * D_STATE + n]);
    const float Dd = Dv[d];

    float h[D_STATE];
    #pragma unroll
    for (int n = 0; n < D_STATE; n++) h[n] = 0.f;

    __shared__ float sBC[SCHUNK][2 * D_STATE];

    for (int l0 = 0; l0 < L_SZ; l0 += SCHUNK) {
        __syncthreads();
        for (int i = tid; i < SCHUNK * 2 * D_STATE; i += blockDim.x) {
            const int t = i >> 5, c = i & 31;
            sBC[t][c] = xdbl[((size_t)b * L_SZ + l0 + t) * XDBL_C + DT_RANK + c];
        }
        __syncthreads();

        for (int t = 0; t < SCHUNK; t++) {
            const int l = l0 + t;
            const size_t base = ((size_t)b * L_SZ + l) * D_INNER + d;
            const float u   = __bfloat162float(xch[base]) + __bfloat162float(xcl[base]);
            const float dtv = dtp[base];
            const float dtu = dtv * u;
            float y = 0.f;
            #pragma unroll
            for (int n = 0; n < D_STATE; n++) {
                const float dA = __expf(dtv * A[n]);
                h[n] = h[n] * dA + dtu * sBC[t][n];
                y += h[n] * sBC[t][D_STATE + n];
            }
            y += u * Dd;
            const int lsrc = dir ? (L_SZ - 1 - l) : l;
            const float zv = g_xz[((size_t)b * L_SZ + lsrc) * E2 + D_INNER + d];
            yout[((size_t)b * L_SZ + lsrc) * D_INNER + d] = y * siluf(zv);
        }
    }
}

// ---------------- Launch ----------------
extern "C" void kernel_launch(void* const* d_in, const int* in_sizes, int n_in,
                              void* d_out, int out_size)
{
    const float* x            = (const float*)d_in[0];
    const float* in_proj_w    = (const float*)d_in[1];
    const float* out_proj_w   = (const float*)d_in[2];
    const float* conv1d_w     = (const float*)d_in[3];
    const float* conv1d_bias  = (const float*)d_in[4];
    const float* x_proj_w     = (const float*)d_in[5];
    const float* dt_proj_w    = (const float*)d_in[6];
    const float* dt_proj_bias = (const float*)d_in[7];
    const float* A_log        = (const float*)d_in[8];
    const float* Dvec         = (const float*)d_in[9];
    const float* conv1d_w_b   = (const float*)d_in[10];
    const float* conv1d_bias_b= (const float*)d_in[11];
    const float* x_proj_w_b   = (const float*)d_in[12];
    const float* dt_proj_w_b  = (const float*)d_in[13];
    const float* dt_proj_bias_b=(const float*)d_in[14];
    const float* A_log_b      = (const float*)d_in[15];
    const float* D_b          = (const float*)d_in[16];
    float* out = (float*)d_out;

    float *p_xz, *p_dt, *p_xdbl, *p_y;
    __nv_bfloat16 *p_xh,*p_xl,*p_wih,*p_wil,*p_woh,*p_wol,*p_wxh,*p_wxl,*p_wdh,*p_wdl;
    __nv_bfloat16 *p_xch,*p_xcl,*p_dtrh,*p_dtrl,*p_ysh,*p_ysl;
    cudaGetSymbolAddress((void**)&p_xz,   g_xz);
    cudaGetSymbolAddress((void**)&p_dt,   g_dt);
    cudaGetSymbolAddress((void**)&p_xdbl, g_xdbl);
    cudaGetSymbolAddress((void**)&p_y,    g_y);
    cudaGetSymbolAddress((void**)&p_xh,  s_xh);   cudaGetSymbolAddress((void**)&p_xl,  s_xl);
    cudaGetSymbolAddress((void**)&p_wih, s_wih);  cudaGetSymbolAddress((void**)&p_wil, s_wil);
    cudaGetSymbolAddress((void**)&p_woh, s_woh);  cudaGetSymbolAddress((void**)&p_wol, s_wol);
    cudaGetSymbolAddress((void**)&p_wxh, s_wxh);  cudaGetSymbolAddress((void**)&p_wxl, s_wxl);
    cudaGetSymbolAddress((void**)&p_wdh, s_wdh);  cudaGetSymbolAddress((void**)&p_wdl, s_wdl);
    cudaGetSymbolAddress((void**)&p_xch, s_xch);  cudaGetSymbolAddress((void**)&p_xcl, s_xcl);
    cudaGetSymbolAddress((void**)&p_dtrh,s_dtrh); cudaGetSymbolAddress((void**)&p_dtrl,s_dtrl);
    cudaGetSymbolAddress((void**)&p_ysh, s_ysh);  cudaGetSymbolAddress((void**)&p_ysl, s_ysl);

    cudaFuncSetAttribute(gemm_sp, cudaFuncAttributeMaxDynamicSharedMemorySize, 2 * STAGE_B);

    const size_t tokDI = (size_t)NTOK * D_INNER;
    const size_t tokXD = (size_t)NTOK * XDBL_C;
    const size_t wx1   = (size_t)XDBL_C * D_INNER;
    const size_t wd1   = (size_t)D_INNER * DT_RANK;
    const size_t dtr1  = (size_t)NTOK * DT_RANK;

    // 0) conversions (weights + x)
    cvt_split<<<4096, 256>>>(x,          p_xh,  p_xl,  NTOK * DIM / 4);
    cvt_split<<<1024, 256>>>(in_proj_w,  p_wih, p_wil, E2 * DIM / 4);
    cvt_split<<< 512, 256>>>(out_proj_w, p_woh, p_wol, DIM * D_INNER / 4);
    cvt_split<<< 128, 256>>>(x_proj_w,   p_wxh, p_wxl, (int)(wx1 / 4));
    cvt_split<<< 128, 256>>>(x_proj_w_b, p_wxh + wx1, p_wxl + wx1, (int)(wx1 / 4));
    cvt_split<<< 128, 256>>>(dt_proj_w,  p_wdh, p_wdl, (int)(wd1 / 4));
    cvt_split<<< 128, 256>>>(dt_proj_w_b,p_wdh + wd1, p_wdl + wd1, (int)(wd1 / 4));

    // 1) in_proj: (16384 x 3072, K=768)
    {
        GArg a{p_xh, p_xl, p_wih, p_wil, nullptr, p_xz};
        dim3 grid(E2 / BN, NTOK / BM, 1);
        gemm_sp<<<grid, 256, 2*STAGE_B>>>(a, a, DIM, DIM, E2, NTOK, E2, DIM, 0);
    }

    // 2) conv + silu -> split bf16 xc
    {
        dim3 grid((unsigned)(((size_t)NTOK * D_INNER + 255) / 256), 2);
        conv_silu_kernel<<<grid, 256>>>(conv1d_w, conv1d_bias, conv1d_w_b, conv1d_bias_b);
    }

    // 3) x_proj both dirs (16384 x 80, K=1536)
    {
        GArg a0{p_xch,         p_xcl,         p_wxh,       p_wxl,       nullptr, p_xdbl};
        GArg a1{p_xch + tokDI, p_xcl + tokDI, p_wxh + wx1, p_wxl + wx1, nullptr, p_xdbl + tokXD};
        dim3 grid(1, NTOK / BM, 2);
        gemm_sp<<<grid, 256, 2*STAGE_B>>>(a0, a1, D_INNER, D_INNER, XDBL_C, NTOK, XDBL_C, D_INNER, 0);
    }

    // 3b) split dt_r columns
    cvt_dtr<<<dim3(768, 2), 256>>>(0);

    // 4) dt_proj both dirs (16384 x 1536, K=48) + softplus
    {
        GArg a0{p_dtrh,        p_dtrl,        p_wdh,       p_wdl,       dt_proj_bias,   p_dt};
        GArg a1{p_dtrh + dtr1, p_dtrl + dtr1, p_wdh + wd1, p_wdl + wd1, dt_proj_bias_b, p_dt + tokDI};
        dim3 grid(D_INNER / BN, NTOK / BM, 2);
        gemm_sp<<<grid, 256, 2*STAGE_B>>>(a0, a1, DT_RANK, DT_RANK, D_INNER, NTOK, D_INNER, DT_RANK, 1);
    }

    // 5) selective scan
    {
        dim3 grid(D_INNER / 128, B_SZ, 2);
        scan_kernel<<<grid, 128>>>(A_log, Dvec, A_log_b, D_b);
    }

    // 5b) ysum = split(y_f + y_b)
    cvt_add_split<<<8192, 256>>>(p_y, p_y + tokDI, p_ysh, p_ysl, (int)(tokDI / 4));

    // 6) out_proj: (16384 x 768, K=1536)
    {
        GArg a{p_ysh, p_ysl, p_woh, p_wol, nullptr, out};
        dim3 grid(DIM / BN, NTOK / BM, 1);
        gemm_sp<<<grid, 256, 2*STAGE_B>>>(a, a, D_INNER, D_INNER, DIM, NTOK, DIM, D_INNER, 0);
    }
}

// round 5
// speedup vs baseline: 1.5425x; 1.0605x over previous
#include <cuda_runtime.h>
#include <cuda_fp16.h>
#include <cuda_bf16.h>
#include <cstdint>

// ---------------- Problem constants ----------------
#define B_SZ     4
#define L_SZ     4096
#define DIM      768
#define D_STATE  16
#define D_CONV   4
#define D_INNER  1536
#define DT_RANK  48
#define E2       (2*D_INNER) // 3072
#define NTOK     (B_SZ*L_SZ) // 16384
#define XDBL_C   (DT_RANK + 2*D_STATE) // 80

// ---------------- Scratch (static, allocation-free) ----------------
__device__ float g_xz  [(size_t)NTOK * E2];            // in_proj out fp32 (x | z)
__device__ float g_dt  [2 * (size_t)NTOK * D_INNER];   // softplus(dt)
__device__ float g_xdbl[2 * (size_t)NTOK * XDBL_C];    // (dt_r | B | C) fp32
__device__ float g_y   [2 * (size_t)NTOK * D_INNER];   // scan out (original l)

// fp16 buffers: activations split hi/lo, weights single
__device__ __align__(16) __half s_xh [(size_t)NTOK * DIM];
__device__ __align__(16) __half s_xl [(size_t)NTOK * DIM];
__device__ __align__(16) __half s_wi [(size_t)E2 * DIM];
__device__ __align__(16) __half s_wo [(size_t)DIM * D_INNER];
__device__ __align__(16) __half s_wx [2 * (size_t)XDBL_C * D_INNER];
__device__ __align__(16) __half s_wd [2 * (size_t)D_INNER * DT_RANK];
__device__ __align__(16) __half s_xch[2 * (size_t)NTOK * D_INNER];
__device__ __align__(16) __half s_xcl[2 * (size_t)NTOK * D_INNER];
__device__ __align__(16) __half s_dtrh[2 * (size_t)NTOK * DT_RANK];
__device__ __align__(16) __half s_dtrl[2 * (size_t)NTOK * DT_RANK];
__device__ __align__(16) __half s_ysh[(size_t)NTOK * D_INNER];
__device__ __align__(16) __half s_ysl[(size_t)NTOK * D_INNER];

// ---------------- helpers ----------------
__device__ __forceinline__ float softplusf(float x) {
    return (x > 20.f) ? x : log1pf(__expf(x));
}
__device__ __forceinline__ float siluf(float x) {
    return x / (1.f + __expf(-x));
}
__device__ __forceinline__ uint32_t smem_u32(const void* p) {
    uint32_t a;
    asm("{ .reg .u64 t; cvta.to.shared.u64 t, %1; cvt.u32.u64 %0, t; }" : "=r"(a) : "l"(p));
    return a;
}
__device__ __forceinline__ void ldsm4(uint32_t* r, uint32_t addr) {
    asm volatile("ldmatrix.sync.aligned.m8n8.x4.shared.b16 {%0,%1,%2,%3}, [%4];"
        : "=r"(r[0]), "=r"(r[1]), "=r"(r[2]), "=r"(r[3]) : "r"(addr));
}
__device__ __forceinline__ void mma_f16(float* c, const uint32_t* a, const uint32_t* b) {
    asm volatile("mma.sync.aligned.m16n8k16.row.col.f32.f16.f16.f32 "
        "{%0,%1,%2,%3}, {%4,%5,%6,%7}, {%8,%9}, {%0,%1,%2,%3};"
        : "+f"(c[0]), "+f"(c[1]), "+f"(c[2]), "+f"(c[3])
        : "r"(a[0]), "r"(a[1]), "r"(a[2]), "r"(a[3]), "r"(b[0]), "r"(b[1]));
}
__device__ __forceinline__ void cp16(uint32_t dst, const void* src, bool pred) {
    const int sz = pred ? 16 : 0;
    asm volatile("cp.async.cg.shared.global [%0], [%1], 16, %2;"
        :: "r"(dst), "l"(src), "r"(sz) : "memory");
}
__device__ __forceinline__ void split2h(float v, __half& h, __half& l) {
    h = __float2half_rn(v);
    l = __float2half_rn(v - __half2float(h));
}

// ---------------- conversion kernels ----------------
__global__ void cvt_split(const float* __restrict__ src,
                          __half* __restrict__ h, __half* __restrict__ l, int n4)
{
    for (int i = blockIdx.x * blockDim.x + threadIdx.x; i < n4; i += gridDim.x * blockDim.x) {
        float4 v = ((const float4*)src)[i];
        __half h0,h1,h2,h3,l0,l1,l2,l3;
        split2h(v.x,h0,l0); split2h(v.y,h1,l1); split2h(v.z,h2,l2); split2h(v.w,h3,l3);
        __half2 hh01{h0,h1}, hh23{h2,h3}, ll01{l0,l1}, ll23{l2,l3};
        ((uint2*)h)[i] = make_uint2(*(uint32_t*)&hh01, *(uint32_t*)&hh23);
        ((uint2*)l)[i] = make_uint2(*(uint32_t*)&ll01, *(uint32_t*)&ll23);
    }
}

__global__ void cvt_h(const float* __restrict__ src, __half* __restrict__ h, int n4)
{
    for (int i = blockIdx.x * blockDim.x + threadIdx.x; i < n4; i += gridDim.x * blockDim.x) {
        float4 v = ((const float4*)src)[i];
        __half2 a{__float2half_rn(v.x), __float2half_rn(v.y)};
        __half2 b{__float2half_rn(v.z), __float2half_rn(v.w)};
        ((uint2*)h)[i] = make_uint2(*(uint32_t*)&a, *(uint32_t*)&b);
    }
}

__global__ void cvt_h2(const float* __restrict__ s0, __half* __restrict__ d0,
                       const float* __restrict__ s1, __half* __restrict__ d1, int n4)
{
    const float* src = blockIdx.y ? s1 : s0;
    __half* h = blockIdx.y ? d1 : d0;
    for (int i = blockIdx.x * blockDim.x + threadIdx.x; i < n4; i += gridDim.x * blockDim.x) {
        float4 v = ((const float4*)src)[i];
        __half2 a{__float2half_rn(v.x), __float2half_rn(v.y)};
        __half2 b{__float2half_rn(v.z), __float2half_rn(v.w)};
        ((uint2*)h)[i] = make_uint2(*(uint32_t*)&a, *(uint32_t*)&b);
    }
}

__global__ void cvt_add_split(const float* __restrict__ a, const float* __restrict__ b,
                              __half* __restrict__ h, __half* __restrict__ l, int n4)
{
    for (int i = blockIdx.x * blockDim.x + threadIdx.x; i < n4; i += gridDim.x * blockDim.x) {
        float4 va = ((const float4*)a)[i];
        float4 vb = ((const float4*)b)[i];
        va.x += vb.x; va.y += vb.y; va.z += vb.z; va.w += vb.w;
        __half h0,h1,h2,h3,l0,l1,l2,l3;
        split2h(va.x,h0,l0); split2h(va.y,h1,l1); split2h(va.z,h2,l2); split2h(va.w,h3,l3);
        __half2 hh01{h0,h1}, hh23{h2,h3}, ll01{l0,l1}, ll23{l2,l3};
        ((uint2*)h)[i] = make_uint2(*(uint32_t*)&hh01, *(uint32_t*)&hh23);
        ((uint2*)l)[i] = make_uint2(*(uint32_t*)&ll01, *(uint32_t*)&ll23);
    }
}

// ---------------- 2-pass fp16-split HMMA GEMM, 3-stage cp.async ----------------
// C = epi( sum_k (Ah+Al)[m,k] * B[n,k] + bias[n] )
#define BM 128
#define BN 128
#define BKC 32
#define PAD 40
#define OFF_AH 0
#define OFF_AL 10240
#define OFF_B  20480
#define STAGE_B 30720
#define NSTAGE 3

struct GArg {
    const __half *Ah, *Al, *Bh;
    const float* bias;
    float* C;
    __half *Dh, *Dl;   // epi==2: dt_r split output
};

__global__ __launch_bounds__(256, 2) void gemm_sp(
    GArg g0, GArg g1, int lda, int ldb, int ldc, int M, int N, int K, int epi)
{
    extern __shared__ char smem[];
    const uint32_t sbase = smem_u32(smem);
    const GArg g = (blockIdx.z == 0) ? g0 : g1;

    const int tid  = threadIdx.x;
    const int lane = tid & 31;
    const int wid  = tid >> 5;
    const int warpM = wid & 1;
    const int warpN = wid >> 1;

    // group-of-8 M rasterization for L2 reuse (gridDim.y % 8 == 0 guaranteed)
    int bmb, bnb;
    {
        const int nbn = gridDim.x;
        const int bid = blockIdx.y * nbn + blockIdx.x;
        const int per = 8 * nbn;
        const int grp = bid / per;
        const int r   = bid % per;
        bmb = grp * 8 + (r % 8);
        bnb = r / 8;
    }
    const int bm = bmb * BM;
    const int bn = bnb * BN;

    float acc[4][4][4];
    #pragma unroll
    for (int f = 0; f < 4; f++)
        #pragma unroll
        for (int gg = 0; gg < 4; gg++)
            #pragma unroll
            for (int i = 0; i < 4; i++) acc[f][gg][i] = 0.f;

    const int aRow = warpM * 64 + (lane & 15);
    const int aCol = (lane >> 4) * 8;
    const int bRow = warpN * 32 + (lane & 7) + ((lane >> 4) & 1) * 8;
    const int bCol = ((lane >> 3) & 1) * 8;

    const int nch = (K + BKC - 1) / BKC;

    auto issue = [&](int c, int buf) {
        const int k0 = c * BKC;
        const uint32_t st = sbase + buf * STAGE_B;
        #pragma unroll
        for (int hh = 0; hh < 2; hh++) {
            const int ch  = tid + 256 * hh;   // 0..511
            const int row = ch >> 2;
            const int c16 = ch & 3;
            const int kk  = k0 + c16 * 8;
            const bool vA = kk < K;
            const bool vB = vA && ((bn + row) < N);
            const size_t ao = vA ? ((size_t)(bm + row) * lda + kk) : 0;
            const size_t bo = vB ? ((size_t)(bn + row) * ldb + kk) : 0;
            const uint32_t so = (uint32_t)(row * (PAD * 2) + c16 * 16);
            cp16(st + OFF_AH + so, g.Ah + ao, vA);
            cp16(st + OFF_AL + so, g.Al + ao, vA);
            cp16(st + OFF_B  + so, g.Bh + bo, vB);
        }
        asm volatile("cp.async.commit_group;" ::: "memory");
    };

    issue(0, 0);
    if (nch > 1) issue(1, 1);
    else asm volatile("cp.async.commit_group;" ::: "memory");

    for (int c = 0; c < nch; c++) {
        asm volatile("cp.async.wait_group 1;" ::: "memory");
        __syncthreads();

        const uint32_t st = sbase + (c % NSTAGE) * STAGE_B;
        #pragma unroll
        for (int ks = 0; ks < 2; ks++) {
            const int kc = ks * 16;
            uint32_t b[4][2], a[4][4];
            #pragma unroll
            for (int p = 0; p < 2; p++) {
                uint32_t r[4];
                ldsm4(r, st + OFF_B + (uint32_t)((bRow + p*16) * PAD + kc + bCol) * 2);
                b[2*p][0] = r[0]; b[2*p][1] = r[1];
                b[2*p+1][0] = r[2]; b[2*p+1][1] = r[3];
            }
            #pragma unroll
            for (int f = 0; f < 4; f++)
                ldsm4(a[f], st + OFF_AH + (uint32_t)((aRow + f*16) * PAD + kc + aCol) * 2);
            #pragma unroll
            for (int f = 0; f < 4; f++)
                #pragma unroll
                for (int gg = 0; gg < 4; gg++) mma_f16(acc[f][gg], a[f], b[gg]);
            #pragma unroll
            for (int f = 0; f < 4; f++)
                ldsm4(a[f], st + OFF_AL + (uint32_t)((aRow + f*16) * PAD + kc + aCol) * 2);
            #pragma unroll
            for (int f = 0; f < 4; f++)
                #pragma unroll
                for (int gg = 0; gg < 4; gg++) mma_f16(acc[f][gg], a[f], b[gg]);
        }
        __syncthreads();
        if (c + 2 < nch) issue(c + 2, (c + 2) % NSTAGE);
        else asm volatile("cp.async.commit_group;" ::: "memory");
    }

    // epilogue
    #pragma unroll
    for (int f = 0; f < 4; f++) {
        const int r0 = bm + warpM * 64 + f * 16 + (lane >> 2);
        #pragma unroll
        for (int gg = 0; gg < 4; gg++) {
            const int col = bn + warpN * 32 + gg * 8 + 2 * (lane & 3);
            if (col < N) {
                float v0 = acc[f][gg][0], v1 = acc[f][gg][1];
                float v2 = acc[f][gg][2], v3 = acc[f][gg][3];
                if (g.bias) {
                    const float b0 = g.bias[col], b1 = g.bias[col + 1];
                    v0 += b0; v1 += b1; v2 += b0; v3 += b1;
                }
                if (epi == 1) {
                    v0 = softplusf(v0); v1 = softplusf(v1);
                    v2 = softplusf(v2); v3 = softplusf(v3);
                }
                *(float2*)(g.C + (size_t)r0 * ldc + col)       = make_float2(v0, v1);
                *(float2*)(g.C + (size_t)(r0 + 8) * ldc + col) = make_float2(v2, v3);
                if (epi == 2 && col < DT_RANK) {
                    __half h0,l0,h1,l1,h2,l2,h3,l3;
                    split2h(v0,h0,l0); split2h(v1,h1,l1);
                    split2h(v2,h2,l2); split2h(v3,h3,l3);
                    __half2 ha{h0,h1}, la{l0,l1}, hb{h2,h3}, lb{l2,l3};
                    *(__half2*)(g.Dh + (size_t)r0 * DT_RANK + col)       = ha;
                    *(__half2*)(g.Dl + (size_t)r0 * DT_RANK + col)       = la;
                    *(__half2*)(g.Dh + (size_t)(r0 + 8) * DT_RANK + col) = hb;
                    *(__half2*)(g.Dl + (size_t)(r0 + 8) * DT_RANK + col) = lb;
                }
            }
        }
    }
}

// ---------------- Causal depthwise conv (k=4) + SiLU -> split fp16 ----------------
__global__ void conv_silu_kernel(
    const float* __restrict__ wf, const float* __restrict__ bf,
    const float* __restrict__ wb, const float* __restrict__ bb)
{
    const int dir = blockIdx.y;
    const size_t idx = (size_t)blockIdx.x * blockDim.x + threadIdx.x;
    if (idx >= (size_t)NTOK * D_INNER) return;
    const int d = (int)(idx % D_INNER);
    const size_t bl = idx / D_INNER;
    const int l = (int)(bl % L_SZ);
    const int b = (int)(bl / L_SZ);

    const float* w = dir ? wb : wf;
    float acc = dir ? bb[d] : bf[d];
    #pragma unroll
    for (int j = 0; j < D_CONV; j++) {
        const int m = l - (D_CONV - 1) + j;
        if (m >= 0) {
            const int src = dir ? (L_SZ - 1 - m) : m;
            acc += w[d * D_CONV + j] * g_xz[((size_t)b * L_SZ + src) * E2 + d];
        }
    }
    const float v = siluf(acc);
    __half h, lo;
    split2h(v, h, lo);
    const size_t o = ((size_t)dir * NTOK + bl) * D_INNER + d;
    s_xch[o] = h;
    s_xcl[o] = lo;
}

// ---------------- Selective scan ----------------
#define SCHUNK 64
__global__ __launch_bounds__(128) void scan_kernel(
    const float* __restrict__ A_log_f, const float* __restrict__ D_f,
    const float* __restrict__ A_log_b, const float* __restrict__ D_b)
{
    const int dir = blockIdx.z;
    const int b   = blockIdx.y;
    const int d   = blockIdx.x * blockDim.x + threadIdx.x;
    const int tid = threadIdx.x;

    const size_t dirTok = (size_t)dir * NTOK;
    const __half* xch = s_xch + dirTok * D_INNER;
    const __half* xcl = s_xcl + dirTok * D_INNER;
    const float* dtp  = g_dt   + dirTok * D_INNER;
    const float* xdbl = g_xdbl + dirTok * XDBL_C;
    float*       yout = g_y    + dirTok * D_INNER;
    const float* Alog = dir ? A_log_b : A_log_f;
    const float* Dv   = dir ? D_b     : D_f;

    float A[D_STATE];
    #pragma unroll
    for (int n = 0; n < D_STATE; n++) A[n] = -__expf(Alog[d * D_STATE + n]);
    const float Dd = Dv[d];

    float h[D_STATE];
    #pragma unroll
    for (int n = 0; n < D_STATE; n++) h[n] = 0.f;

    __shared__ float sBC[SCHUNK][2 * D_STATE];

    for (int l0 = 0; l0 < L_SZ; l0 += SCHUNK) {
        __syncthreads();
        for (int i = tid; i < SCHUNK * 2 * D_STATE; i += blockDim.x) {
            const int t = i >> 5, c = i & 31;
            sBC[t][c] = xdbl[((size_t)b * L_SZ + l0 + t) * XDBL_C + DT_RANK + c];
        }
        __syncthreads();

        for (int t = 0; t < SCHUNK; t++) {
            const int l = l0 + t;
            const size_t base = ((size_t)b * L_SZ + l) * D_INNER + d;
            const float u   = __half2float(xch[base]) + __half2float(xcl[base]);
            const float dtv = dtp[base];
            const float dtu = dtv * u;
            float y = 0.f;
            #pragma unroll
            for (int n = 0; n < D_STATE; n++) {
                const float dA = __expf(dtv * A[n]);
                h[n] = h[n] * dA + dtu * sBC[t][n];
                y += h[n] * sBC[t][D_STATE + n];
            }
            y += u * Dd;
            const int lsrc = dir ? (L_SZ - 1 - l) : l;
            const float zv = g_xz[((size_t)b * L_SZ + lsrc) * E2 + D_INNER + d];
            yout[((size_t)b * L_SZ + lsrc) * D_INNER + d] = y * siluf(zv);
        }
    }
}

// ---------------- Launch ----------------
extern "C" void kernel_launch(void* const* d_in, const int* in_sizes, int n_in,
                              void* d_out, int out_size)
{
    const float* x            = (const float*)d_in[0];
    const float* in_proj_w    = (const float*)d_in[1];
    const float* out_proj_w   = (const float*)d_in[2];
    const float* conv1d_w     = (const float*)d_in[3];
    const float* conv1d_bias  = (const float*)d_in[4];
    const float* x_proj_w     = (const float*)d_in[5];
    const float* dt_proj_w    = (const float*)d_in[6];
    const float* dt_proj_bias = (const float*)d_in[7];
    const float* A_log        = (const float*)d_in[8];
    const float* Dvec         = (const float*)d_in[9];
    const float* conv1d_w_b   = (const float*)d_in[10];
    const float* conv1d_bias_b= (const float*)d_in[11];
    const float* x_proj_w_b   = (const float*)d_in[12];
    const float* dt_proj_w_b  = (const float*)d_in[13];
    const float* dt_proj_bias_b=(const float*)d_in[14];
    const float* A_log_b      = (const float*)d_in[15];
    const float* D_b          = (const float*)d_in[16];
    float* out = (float*)d_out;

    float *p_xz, *p_dt, *p_xdbl, *p_y;
    __half *p_xh,*p_xl,*p_wi,*p_wo,*p_wx,*p_wd,*p_xch,*p_xcl,*p_dtrh,*p_dtrl,*p_ysh,*p_ysl;
    cudaGetSymbolAddress((void**)&p_xz,   g_xz);
    cudaGetSymbolAddress((void**)&p_dt,   g_dt);
    cudaGetSymbolAddress((void**)&p_xdbl, g_xdbl);
    cudaGetSymbolAddress((void**)&p_y,    g_y);
    cudaGetSymbolAddress((void**)&p_xh,  s_xh);   cudaGetSymbolAddress((void**)&p_xl,  s_xl);
    cudaGetSymbolAddress((void**)&p_wi,  s_wi);
    cudaGetSymbolAddress((void**)&p_wo,  s_wo);
    cudaGetSymbolAddress((void**)&p_wx,  s_wx);
    cudaGetSymbolAddress((void**)&p_wd,  s_wd);
    cudaGetSymbolAddress((void**)&p_xch, s_xch);  cudaGetSymbolAddress((void**)&p_xcl, s_xcl);
    cudaGetSymbolAddress((void**)&p_dtrh,s_dtrh); cudaGetSymbolAddress((void**)&p_dtrl,s_dtrl);
    cudaGetSymbolAddress((void**)&p_ysh, s_ysh);  cudaGetSymbolAddress((void**)&p_ysl, s_ysl);

    cudaFuncSetAttribute(gemm_sp, cudaFuncAttributeMaxDynamicSharedMemorySize, NSTAGE * STAGE_B);

    const size_t tokDI = (size_t)NTOK * D_INNER;
    const size_t tokXD = (size_t)NTOK * XDBL_C;
    const size_t wx1   = (size_t)XDBL_C * D_INNER;
    const size_t wd1   = (size_t)D_INNER * DT_RANK;
    const size_t dtr1  = (size_t)NTOK * DT_RANK;

    // launches 1-5: conversions (in_proj GEMM must be launch #6 for ncu -s 5 -c 1)
    cvt_split<<<2048, 256>>>(x, p_xh, p_xl, NTOK * DIM / 4);
    cvt_h<<<1024, 256>>>(in_proj_w,  p_wi, E2 * DIM / 4);
    cvt_h<<< 512, 256>>>(out_proj_w, p_wo, DIM * D_INNER / 4);
    cvt_h2<<<dim3(128, 2), 256>>>(x_proj_w, p_wx, x_proj_w_b, p_wx + wx1, (int)(wx1 / 4));
    cvt_h2<<<dim3(128, 2), 256>>>(dt_proj_w, p_wd, dt_proj_w_b, p_wd + wd1, (int)(wd1 / 4));

    // 6) in_proj (16384 x 3072, K=768)  <-- profiled launch
    {
        GArg a{p_xh, p_xl, p_wi, nullptr, p_xz, nullptr, nullptr};
        dim3 grid(E2 / BN, NTOK / BM, 1);
        gemm_sp<<<grid, 256, NSTAGE*STAGE_B>>>(a, a, DIM, DIM, E2, NTOK, E2, DIM, 0);
    }

    // 7) conv + silu -> split fp16
    {
        dim3 grid((unsigned)(((size_t)NTOK * D_INNER + 255) / 256), 2);
        conv_silu_kernel<<<grid, 256>>>(conv1d_w, conv1d_bias, conv1d_w_b, conv1d_bias_b);
    }

    // 8) x_proj both dirs (16384 x 80, K=1536), epilogue also splits dt_r
    {
        GArg a0{p_xch,         p_xcl,         p_wx,       nullptr, p_xdbl,         p_dtrh,        p_dtrl};
        GArg a1{p_xch + tokDI, p_xcl + tokDI, p_wx + wx1, nullptr, p_xdbl + tokXD, p_dtrh + dtr1, p_dtrl + dtr1};
        dim3 grid(1, NTOK / BM, 2);
        gemm_sp<<<grid, 256, NSTAGE*STAGE_B>>>(a0, a1, D_INNER, D_INNER, XDBL_C, NTOK, XDBL_C, D_INNER, 2);
    }

    // 9) dt_proj both dirs (16384 x 1536, K=48) + softplus
    {
        GArg a0{p_dtrh,        p_dtrl,        p_wd,       dt_proj_bias,   p_dt,         nullptr, nullptr};
        GArg a1{p_dtrh + dtr1, p_dtrl + dtr1, p_wd + wd1, dt_proj_bias_b, p_dt + tokDI, nullptr, nullptr};
        dim3 grid(D_INNER / BN, NTOK / BM, 2);
        gemm_sp<<<grid, 256, NSTAGE*STAGE_B>>>(a0, a1, DT_RANK, DT_RANK, D_INNER, NTOK, D_INNER, DT_RANK, 1);
    }

    // 10) selective scan
    {
        dim3 grid(D_INNER / 128, B_SZ, 2);
        scan_kernel<<<grid, 128>>>(A_log, Dvec, A_log_b, D_b);
    }

    // 11) ysum = split(y_f + y_b)
    cvt_add_split<<<2048, 256>>>(p_y, p_y + tokDI, p_ysh, p_ysl, (int)(tokDI / 4));

    // 12) out_proj (16384 x 768, K=1536)
    {
        GArg a{p_ysh, p_ysl, p_wo, nullptr, out, nullptr, nullptr};
        dim3 grid(DIM / BN, NTOK / BM, 1);
        gemm_sp<<<grid, 256, NSTAGE*STAGE_B>>>(a, a, D_INNER, D_INNER, DIM, NTOK, DIM, D_INNER, 0);
    }
}